// round 15
// baseline (speedup 1.0000x reference)
#include <cuda_runtime.h>
#include <cstdint>

// Problem constants
#define BATCH     64
#define NPER      786432
#define VPER      (NPER / 4)              // 196608 int4 per row
#define LEVELS    256
#define HTHREADS  256
#define BPR       8                       // hist CTAs per row -> 512 CTAs total
#define V_PER_CTA (VPER / BPR)            // 24576 int4
#define HALF_V    (V_PER_CTA / 2)         // 12288 int4 per stream
#define ITERS     (HALF_V / HTHREADS)     // 48 iterations, 2 int4 each

// All statically zero; every launch returns them to zero -> graph-replay safe.
__device__ unsigned int g_hist[BATCH * LEVELS];   // per-row histograms
__device__ unsigned int g_cnt[BATCH];             // arrival tickets per row
__device__ unsigned int g_flag[BATCH];            // row-complete flag
__device__ unsigned int g_done[BATCH];            // broadcast-done tickets

// ---------------------------------------------------------------------------
// Round-11 proven structure; ONLY change: mainloop processes TWO independent
// streams (CTA-region halves) per thread -> up to 8 front-batched LDG.128s
// per unrolled group (reg budget ~63 <= 64 cap) -> higher per-warp MLP.
//
// Co-residency: launch_bounds(256,4), 32KB smem -> >=4 CTAs/SM guaranteed,
// 512 CTAs <= 592 slots -> one resident wave -> the flag spin cannot deadlock.
// ---------------------------------------------------------------------------
__global__ void __launch_bounds__(HTHREADS, 4)
fused_kernel(const int4* __restrict__ x, float4* __restrict__ out) {
    __shared__ unsigned int sh[LEVELS * 32];   // 32 KB

    #pragma unroll
    for (int i = threadIdx.x; i < LEVELS * 32; i += HTHREADS) sh[i] = 0u;
    __syncthreads();

    const unsigned lane = threadIdx.x & 31u;
    unsigned int hbase = (unsigned int)__cvta_generic_to_shared(sh) + (lane << 2);

    const int b = blockIdx.y;
    const int i = blockIdx.x;
    const int4* __restrict__ blk =
        x + (size_t)b * VPER + (size_t)i * V_PER_CTA;

    #pragma unroll 4
    for (int it = 0; it < ITERS; it++) {
        int4 v0 = blk[it * HTHREADS + threadIdx.x];
        int4 v1 = blk[HALF_V + it * HTHREADS + threadIdx.x];
        asm volatile("red.shared.add.u32 [%0], %1;"
                     :: "r"(hbase + ((unsigned)v0.x << 7)), "r"(1u) : "memory");
        asm volatile("red.shared.add.u32 [%0], %1;"
                     :: "r"(hbase + ((unsigned)v0.y << 7)), "r"(1u) : "memory");
        asm volatile("red.shared.add.u32 [%0], %1;"
                     :: "r"(hbase + ((unsigned)v0.z << 7)), "r"(1u) : "memory");
        asm volatile("red.shared.add.u32 [%0], %1;"
                     :: "r"(hbase + ((unsigned)v0.w << 7)), "r"(1u) : "memory");
        asm volatile("red.shared.add.u32 [%0], %1;"
                     :: "r"(hbase + ((unsigned)v1.x << 7)), "r"(1u) : "memory");
        asm volatile("red.shared.add.u32 [%0], %1;"
                     :: "r"(hbase + ((unsigned)v1.y << 7)), "r"(1u) : "memory");
        asm volatile("red.shared.add.u32 [%0], %1;"
                     :: "r"(hbase + ((unsigned)v1.z << 7)), "r"(1u) : "memory");
        asm volatile("red.shared.add.u32 [%0], %1;"
                     :: "r"(hbase + ((unsigned)v1.w << 7)), "r"(1u) : "memory");
    }
    __syncthreads();

    // Reduce the 32 lane-copies of bin t (rotated start -> conflict-free),
    // one spread-address global RED per bin.
    {
        const unsigned t = threadIdx.x;
        unsigned int s = 0;
        #pragma unroll
        for (int c = 0; c < 32; c++) s += sh[t * 32 + ((c + t) & 31u)];
        atomicAdd(&g_hist[(unsigned)b * LEVELS + t], s);
    }

    // ---- Row-completion sync ----
    __threadfence();                 // publish this thread's REDG
    __syncthreads();                 // all threads of CTA published
    if (threadIdx.x == 0) {
        unsigned t = atomicAdd(&g_cnt[b], 1u);
        if (t == BPR - 1) atomicExch(&g_flag[b], 1u);   // release row
        while (*(volatile unsigned*)&g_flag[b] == 0u) __nanosleep(64);
    }
    __syncthreads();
    __threadfence();                 // acquire: g_hist row now complete

    // ---- Broadcast bins [i*32, i*32+32) of row b ----
    float* shf = (float*)sh;         // reuse smem
    const unsigned binBase = (unsigned)b * LEVELS + (unsigned)i * 32u;
    if (threadIdx.x < 32)
        shf[threadIdx.x] = (float)g_hist[binBase + threadIdx.x];
    __syncthreads();

    float4* __restrict__ dst =
        out + ((size_t)b * LEVELS + (size_t)i * 32u) * (LEVELS / 4);
    #pragma unroll
    for (int k = threadIdx.x; k < 32 * (LEVELS / 4); k += HTHREADS) {
        float v = shf[k >> 6];
        dst[k] = make_float4(v, v, v, v);
    }

    // reset this CTA's own g_hist entries (sole reader was this CTA)
    if (threadIdx.x < 32) g_hist[binBase + threadIdx.x] = 0u;

    // last CTA of the row to finish resets the row's sync state
    if (threadIdx.x == 0) {
        __threadfence();
        unsigned d = atomicAdd(&g_done[b], 1u);
        if (d == BPR - 1) {
            g_cnt[b]  = 0u;
            g_flag[b] = 0u;
            g_done[b] = 0u;
            __threadfence();
        }
    }
}

// ---------------------------------------------------------------------------
extern "C" void kernel_launch(void* const* d_in, const int* in_sizes, int n_in,
                              void* d_out, int out_size) {
    const int4* x = (const int4*)d_in[0];
    float4* out = (float4*)d_out;

    dim3 grid(BPR, BATCH);
    fused_kernel<<<grid, HTHREADS>>>(x, out);
}

// round 16
// speedup vs baseline: 1.0658x; 1.0658x over previous
#include <cuda_runtime.h>
#include <cstdint>

// Problem constants
#define BATCH     64
#define NPER      786432
#define VPER      (NPER / 4)              // 196608 int4 per row
#define LEVELS    256
#define HTHREADS  256
#define BPR       8                       // hist CTAs per row -> 512 CTAs total
#define V_PER_CTA (VPER / BPR)            // 24576 int4
#define ITERS     (V_PER_CTA / HTHREADS)  // 96 int4 per thread

// All statically zero; every launch returns them to zero -> graph-replay safe.
__device__ unsigned int g_hist[BATCH * LEVELS];   // per-row histograms
__device__ unsigned int g_cnt[BATCH];             // arrival tickets per row
__device__ unsigned int g_flag[BATCH];            // row-complete flag
__device__ unsigned int g_done[BATCH];            // broadcast-done tickets

// ---------------------------------------------------------------------------
// Round-11 proven structure, byte-identical except: mainloop load uses __ldcg
// (L1-bypass, L2-default) -- read-once stream shouldn't allocate in L1.
//
// Co-residency: launch_bounds(256,4), 32KB smem -> >=4 CTAs/SM guaranteed,
// 512 CTAs <= 592 slots -> one resident wave -> the flag spin cannot deadlock.
// ---------------------------------------------------------------------------
__global__ void __launch_bounds__(HTHREADS, 4)
fused_kernel(const int4* __restrict__ x, float4* __restrict__ out) {
    __shared__ unsigned int sh[LEVELS * 32];   // 32 KB

    #pragma unroll
    for (int i = threadIdx.x; i < LEVELS * 32; i += HTHREADS) sh[i] = 0u;
    __syncthreads();

    const unsigned lane = threadIdx.x & 31u;
    unsigned int hbase = (unsigned int)__cvta_generic_to_shared(sh) + (lane << 2);

    const int b = blockIdx.y;
    const int i = blockIdx.x;
    const int4* __restrict__ blk =
        x + (size_t)b * VPER + (size_t)i * V_PER_CTA;

    #pragma unroll 4
    for (int it = 0; it < ITERS; it++) {
        int4 v = __ldcg(&blk[it * HTHREADS + threadIdx.x]);
        asm volatile("red.shared.add.u32 [%0], %1;"
                     :: "r"(hbase + ((unsigned)v.x << 7)), "r"(1u) : "memory");
        asm volatile("red.shared.add.u32 [%0], %1;"
                     :: "r"(hbase + ((unsigned)v.y << 7)), "r"(1u) : "memory");
        asm volatile("red.shared.add.u32 [%0], %1;"
                     :: "r"(hbase + ((unsigned)v.z << 7)), "r"(1u) : "memory");
        asm volatile("red.shared.add.u32 [%0], %1;"
                     :: "r"(hbase + ((unsigned)v.w << 7)), "r"(1u) : "memory");
    }
    __syncthreads();

    // Reduce the 32 lane-copies of bin t (rotated start -> conflict-free),
    // one spread-address global RED per bin.
    {
        const unsigned t = threadIdx.x;
        unsigned int s = 0;
        #pragma unroll
        for (int c = 0; c < 32; c++) s += sh[t * 32 + ((c + t) & 31u)];
        atomicAdd(&g_hist[(unsigned)b * LEVELS + t], s);
    }

    // ---- Row-completion sync ----
    __threadfence();                 // publish this thread's REDG
    __syncthreads();                 // all threads of CTA published
    if (threadIdx.x == 0) {
        unsigned t = atomicAdd(&g_cnt[b], 1u);
        if (t == BPR - 1) atomicExch(&g_flag[b], 1u);   // release row
        while (*(volatile unsigned*)&g_flag[b] == 0u) __nanosleep(64);
    }
    __syncthreads();
    __threadfence();                 // acquire: g_hist row now complete

    // ---- Broadcast bins [i*32, i*32+32) of row b ----
    float* shf = (float*)sh;         // reuse smem
    const unsigned binBase = (unsigned)b * LEVELS + (unsigned)i * 32u;
    if (threadIdx.x < 32)
        shf[threadIdx.x] = (float)g_hist[binBase + threadIdx.x];
    __syncthreads();

    float4* __restrict__ dst =
        out + ((size_t)b * LEVELS + (size_t)i * 32u) * (LEVELS / 4);
    #pragma unroll
    for (int k = threadIdx.x; k < 32 * (LEVELS / 4); k += HTHREADS) {
        float v = shf[k >> 6];
        dst[k] = make_float4(v, v, v, v);
    }

    // reset this CTA's own g_hist entries (sole reader was this CTA)
    if (threadIdx.x < 32) g_hist[binBase + threadIdx.x] = 0u;

    // last CTA of the row to finish resets the row's sync state
    if (threadIdx.x == 0) {
        __threadfence();
        unsigned d = atomicAdd(&g_done[b], 1u);
        if (d == BPR - 1) {
            g_cnt[b]  = 0u;
            g_flag[b] = 0u;
            g_done[b] = 0u;
            __threadfence();
        }
    }
}

// ---------------------------------------------------------------------------
extern "C" void kernel_launch(void* const* d_in, const int* in_sizes, int n_in,
                              void* d_out, int out_size) {
    const int4* x = (const int4*)d_in[0];
    float4* out = (float4*)d_out;

    dim3 grid(BPR, BATCH);
    fused_kernel<<<grid, HTHREADS>>>(x, out);
}